// round 5
// baseline (speedup 1.0000x reference)
#include <cuda_runtime.h>
#include <cuda_bf16.h>

// EmbeddedGCN: out[b,i,o] = relu( sum_j adj[b,i,j] * (concat(s1,s2)[b,i,j,:] @ W)[o] + bias[o] )
// Linearity rewrite:
//   y[b,i,f]   = sum_j adj[b,i,j] * concat(s1,s2)[b,i,j,f]     (gated gather-reduce)
//   out[b,i,o] = relu( sum_f y[f]*W[f,o] + bias[o]*rowsum(adj) )
//
// B=16, M=128, FE=64 (concat -> 128), FO=128.
// Block = 512 threads (16 warps), RPB=8 rows, TWO warps per row. Grid = 256.
// Warp pair (2r, 2r+1) splits the compacted neighbor list in alternating
// batches of 4 (MLP-4 each, 8 aggregate per row). launch_bounds(512,2) keeps
// 2 blocks/SM resident (~28 warps/SM vs 14 in R3).

#define BM 128
#define FE 64
#define FT 128
#define FO 128
#define RPB 8     // rows per block
#define NW 16     // warps per block

__global__ __launch_bounds__(512, 2)
void gcn_fused3(const float* __restrict__ s1,
                const float* __restrict__ s2,
                const float* __restrict__ adj,
                const float* __restrict__ W,
                const float* __restrict__ bias,
                float* __restrict__ out)
{
    __shared__ int   jidx_s[RPB][BM];
    __shared__ float aval_s[RPB][BM];
    __shared__ float part_s[NW][FT];
    __shared__ float y_s[RPB][FT];
    __shared__ float rowsum_s[RPB];

    const int tid  = threadIdx.x;        // 0..511
    const int lane = tid & 31;
    const int w    = tid >> 5;           // 0..15
    const int r    = w >> 1;             // local row 0..7
    const int half = w & 1;              // which half of the neighbor list
    const int bi0  = blockIdx.x * RPB;
    const int row  = bi0 + r;            // flat b*M + i

    // ---- Phase 1a: adjacency load + warp-prefix compaction ----
    // Both warps of a pair do identical work and write identical values
    // (benign duplicate writes); each warp then only depends on its own writes.
    const float4 av = *(const float4*)(adj + (size_t)row * BM + lane * 4);
    int   cnt  = 0;
    float rsum = 0.0f;
    {
        const unsigned lt = (1u << lane) - 1u;
        #pragma unroll
        for (int q = 0; q < 4; q++) {
            const float a = (q == 0) ? av.x : (q == 1) ? av.y : (q == 2) ? av.z : av.w;
            const unsigned m = __ballot_sync(0xFFFFFFFFu, a != 0.0f);
            if (a != 0.0f) {
                const int pos = cnt + __popc(m & lt);
                jidx_s[r][pos] = lane * 4 + q;
                aval_s[r][pos] = a;
            }
            cnt  += __popc(m);
            rsum += a;
        }
        #pragma unroll
        for (int off = 16; off > 0; off >>= 1)
            rsum += __shfl_xor_sync(0xFFFFFFFFu, rsum, off);
        if (lane == 0 && half == 0) rowsum_s[r] = rsum;
    }
    __syncwarp();

    // ---- Phase 1b: gated gather-reduce; this warp takes alternating 4-batches ----
    // lane -> one float4 of the 128-wide concat row:
    //   lanes 0..15  -> s1, float4 idx = lane        (features 0..63)
    //   lanes 16..31 -> s2, float4 idx = lane - 16   (features 64..127)
    const float4* base4;
    {
        const size_t row0 = (size_t)row * (size_t)(BM * FE);
        base4 = (lane < 16) ? ((const float4*)(s1 + row0) + lane)
                            : ((const float4*)(s2 + row0) + (lane - 16));
    }

    float4 acc = make_float4(0.f, 0.f, 0.f, 0.f);
    int k = half * 4;
    for (; k + 4 <= cnt; k += 8) {
        int   j[4];
        float a[4];
        float4 v[4];
        #pragma unroll
        for (int t = 0; t < 4; t++) { j[t] = jidx_s[r][k + t]; a[t] = aval_s[r][k + t]; }
        #pragma unroll
        for (int t = 0; t < 4; t++) v[t] = __ldg(base4 + (size_t)j[t] * 16);
        #pragma unroll
        for (int t = 0; t < 4; t++) {
            acc.x = fmaf(a[t], v[t].x, acc.x);
            acc.y = fmaf(a[t], v[t].y, acc.y);
            acc.z = fmaf(a[t], v[t].z, acc.z);
            acc.w = fmaf(a[t], v[t].w, acc.w);
        }
    }
    // Tail: [k, cnt) has <4 elements and is owned by exactly one half.
    for (int t = k; t < cnt; t++) {
        const int   j = jidx_s[r][t];
        const float a = aval_s[r][t];
        const float4 v = __ldg(base4 + (size_t)j * 16);
        acc.x = fmaf(a, v.x, acc.x);
        acc.y = fmaf(a, v.y, acc.y);
        acc.z = fmaf(a, v.z, acc.z);
        acc.w = fmaf(a, v.w, acc.w);
    }

    {
        const int fb = (lane < 16) ? (lane * 4) : (FE + (lane - 16) * 4);
        *(float4*)&part_s[w][fb] = acc;
    }
    __syncthreads();

    // ---- Combine the two partials per row into y_s ----
    {
        float* yp = &y_s[0][0];
        const float* pp = &part_s[0][0];
        #pragma unroll
        for (int i = tid; i < RPB * FT; i += 512) {
            const int rr = i >> 7;
            const int ff = i & (FT - 1);
            yp[i] = pp[(2 * rr) * FT + ff] + pp[(2 * rr + 1) * FT + ff];
        }
    }
    __syncthreads();

    // ---- Phase 2: out[r,o] = relu( y[r,:] @ W[:,o] + bias[o]*rowsum[r] ) ----
    // 512 threads: o = tid&127, group g = tid>>7 owns rows {2g, 2g+1}.
    const int o  = tid & (FO - 1);
    const int g  = tid >> 7;             // 0..3
    const int r0 = g * 2;

    float accO[2];
    {
        const float bo = __ldg(bias + o);
        accO[0] = bo * rowsum_s[r0];
        accO[1] = bo * rowsum_s[r0 + 1];
    }

    #pragma unroll 8
    for (int f = 0; f < FT; f += 4) {
        const float w0 = __ldg(W + (f + 0) * FO + o);
        const float w1 = __ldg(W + (f + 1) * FO + o);
        const float w2 = __ldg(W + (f + 2) * FO + o);
        const float w3 = __ldg(W + (f + 3) * FO + o);
        #pragma unroll
        for (int q = 0; q < 2; q++) {
            const float4 y = *(const float4*)&y_s[r0 + q][f];
            accO[q] = fmaf(y.x, w0, accO[q]);
            accO[q] = fmaf(y.y, w1, accO[q]);
            accO[q] = fmaf(y.z, w2, accO[q]);
            accO[q] = fmaf(y.w, w3, accO[q]);
        }
    }

    #pragma unroll
    for (int q = 0; q < 2; q++)
        out[(size_t)(bi0 + r0 + q) * FO + o] = fmaxf(accO[q], 0.0f);
}

extern "C" void kernel_launch(void* const* d_in, const int* in_sizes, int n_in,
                              void* d_out, int out_size)
{
    const float* s1   = (const float*)d_in[0];  // (16,128,128,64)
    const float* s2   = (const float*)d_in[1];  // (16,128,128,64)
    const float* adj  = (const float*)d_in[2];  // (16,128,128)
    const float* W    = (const float*)d_in[3];  // (128,128)
    const float* bias = (const float*)d_in[4];  // (128,)
    float* out = (float*)d_out;                 // (16,128,128)

    gcn_fused3<<<(16 * 128) / RPB, 512>>>(s1, s2, adj, W, bias, out);
}